// round 9
// baseline (speedup 1.0000x reference)
#include <cuda_runtime.h>
#include <cuda_bf16.h>
#include <cstdint>
#include <cstddef>

// ============================================================================
// QLinear via int8 IMMA (mma.sync m16n8k32 s8.s8.s32) — exact integer math.
// w_s = max|W|/127; b_s = w_s*a_s; out = (x_int @ w_int^T + b_int) * b_s
// R9 = R8 resubmit (R8 bench was the recurring infra failure, not kernel):
//   GEMM core = R6 shape (8 warps, 32x64 warp tile, 2 CTA/SM — measured best).
//   quant_x fused into the GEMM kernel as persistent producer/consumer.
//   Hardening vs R8: fixed grid=296 (no host attr query), __nanosleep spin.
// ============================================================================

#define DEV_INLINE __device__ __forceinline__

namespace {
constexpr int NTOK = 32768;
constexpr int DIN  = 768;
constexpr int DOUT = 768;
constexpr long long NM = (long long)NTOK * DOUT;

constexpr int BM = 128;
constexpr int BN = 128;
constexpr int BK = 128;               // bytes of K per stage (int8)
constexpr int KT = DIN / BK;          // 6
constexpr int STAGES = 3;
constexpr int THREADS = 256;

constexpr int MBLKS  = NTOK / BM;     // 256 m-blocks
constexpr int NBLKS  = DOUT / BN;     // 6
constexpr int NTILES = MBLKS * NBLKS; // 1536
constexpr int GRID   = 296;           // 2 x 148 SMs; >= MBLKS (writers resident)

constexpr int A_BYTES = BM * 128;     // 16384 (XOR swizzle, no pad)
constexpr int B_BYTES = BN * 128;     // 16384
constexpr int STAGE_BYTES = A_BYTES + B_BYTES;        // 32768
constexpr int SMEM_BYTES  = STAGES * STAGE_BYTES;     // 98304 -> 2 CTAs/SM
} // namespace

// ---------------- device scratch (static: no runtime allocation) ------------
__device__ __align__(16) int8_t g_xq[(size_t)NTOK * DIN]; // 25.2 MB
__device__ __align__(16) int8_t g_wq[(size_t)DOUT * DIN]; // 0.59 MB
__device__ __align__(16) float  g_bint[DOUT];
__device__ int g_flags[MBLKS];                            // per-m-block ready
__device__ unsigned int g_wmax_bits;                      // zero-init; atomicMax idempotent
__device__ float g_bs;

// ---------------- PTX helpers ------------------------------------------------
DEV_INLINE uint32_t smem_u32(const void* p) {
    uint32_t a;
    asm("{ .reg .u64 t; cvta.to.shared.u64 t, %1; cvt.u32.u64 %0, t; }" : "=r"(a) : "l"(p));
    return a;
}

#define CP16(dst, src) \
    asm volatile("cp.async.cg.shared.global [%0], [%1], 16;" :: "r"(dst), "l"(src))
#define CP_COMMIT() asm volatile("cp.async.commit_group;" ::: "memory")
#define CP_WAIT(n)  asm volatile("cp.async.wait_group %0;" :: "n"(n) : "memory")

#define LDSM_X4(r, addr)                                                        \
    asm volatile("ldmatrix.sync.aligned.m8n8.x4.shared.b16 {%0,%1,%2,%3}, [%4];" \
        : "=r"((r)[0]), "=r"((r)[1]), "=r"((r)[2]), "=r"((r)[3]) : "r"(addr))

#define IMMA(d, a, b0, b1)                                                      \
    asm volatile("mma.sync.aligned.m16n8k32.row.col.s32.s8.s8.s32 "             \
        "{%0,%1,%2,%3}, {%4,%5,%6,%7}, {%8,%9}, {%0,%1,%2,%3};"                 \
        : "+r"((d)[0]), "+r"((d)[1]), "+r"((d)[2]), "+r"((d)[3])                \
        : "r"((a)[0]), "r"((a)[1]), "r"((a)[2]), "r"((a)[3]), "r"(b0), "r"(b1))

// ---------------- quant helpers ----------------------------------------------
DEV_INLINE float q8f(float x, float s) {
    return fminf(fmaxf(rintf(__fdiv_rn(x, s)), -128.f), 127.f);
}
DEV_INLINE uint32_t pack4(float a, float b, float c, float d) {
    return (uint32_t)((int)a & 0xff) | ((uint32_t)((int)b & 0xff) << 8) |
           ((uint32_t)((int)c & 0xff) << 16) | ((uint32_t)((int)d & 0xff) << 24);
}

// ---------------- small kernels ----------------------------------------------
__global__ void qlinear_wmax(const float* __restrict__ w) {
    float m = 0.f;
    const float4* w4 = reinterpret_cast<const float4*>(w);
    int n4 = (DOUT * DIN) >> 2;
    for (int j = blockIdx.x * blockDim.x + threadIdx.x; j < n4; j += gridDim.x * blockDim.x) {
        float4 v = w4[j];
        m = fmaxf(m, fmaxf(fmaxf(fabsf(v.x), fabsf(v.y)), fmaxf(fabsf(v.z), fabsf(v.w))));
    }
    #pragma unroll
    for (int o = 16; o; o >>= 1) m = fmaxf(m, __shfl_xor_sync(0xffffffffu, m, o));
    if ((threadIdx.x & 31) == 0) atomicMax(&g_wmax_bits, __float_as_uint(m));
}

// fused: finalize + quantize W + quantize bias + zero flags + out tail
__global__ void qlinear_prep(const float* __restrict__ w,
                             const float* __restrict__ bias,
                             const float* __restrict__ a_s,
                             float* __restrict__ out, long long out_size) {
    const float ws = __fdiv_rn(__uint_as_float(g_wmax_bits), 127.0f);
    const float bs = __fmul_rn(ws, a_s[0]);

    if (blockIdx.x == 0) {
        if (threadIdx.x == 0) g_bs = bs;
        for (long long i = NM + threadIdx.x; i < out_size; i += blockDim.x) out[i] = bs;
        for (int i = threadIdx.x; i < DOUT; i += blockDim.x) {
            float q = rintf(__fdiv_rn(bias[i], bs));
            g_bint[i] = fminf(fmaxf(q, -2147483648.f), 2147483648.f);
        }
        for (int i = threadIdx.x; i < MBLKS; i += blockDim.x) g_flags[i] = 0;
    }

    const float4* w4 = reinterpret_cast<const float4*>(w);
    uint32_t* dst = reinterpret_cast<uint32_t*>(g_wq);
    int n4 = (DOUT * DIN) >> 2;
    for (int j = blockIdx.x * blockDim.x + threadIdx.x; j < n4; j += gridDim.x * blockDim.x) {
        float4 v = w4[j];
        dst[j] = pack4(q8f(v.x, ws), q8f(v.y, ws), q8f(v.z, ws), q8f(v.w, ws));
    }
}

// ---------------- fused quant_x + GEMM ---------------------------------------
// XOR swizzle: byte chunk c (16B units, 0..7 within a 128B row) -> c ^ (row&7).
DEV_INLINE uint32_t swz(uint32_t row, uint32_t c16) {
    return row * 128u + ((c16 ^ (row & 7u)) << 4);
}

DEV_INLINE void load_stage(uint32_t sbase, const int8_t* gA, const int8_t* gB,
                           int kt, int tid) {
    const int kbase = kt * BK;
    #pragma unroll
    for (int j = 0; j < 4; j++) {          // A: 128 rows x 8 chunks of 16B = 1024
        int idx = tid + j * THREADS;
        uint32_t r = idx >> 3, c = idx & 7;
        CP16(sbase + swz(r, c), gA + (size_t)r * DIN + kbase + c * 16);
    }
    #pragma unroll
    for (int j = 0; j < 4; j++) {          // B: 128 rows x 8 chunks of 16B = 1024
        int idx = tid + j * THREADS;
        uint32_t r = idx >> 3, c = idx & 7;
        CP16(sbase + A_BYTES + swz(r, c), gB + (size_t)r * DIN + kbase + c * 16);
    }
    CP_COMMIT();
}

__global__ __launch_bounds__(THREADS, 2) void qlinear_fused(
        const float* __restrict__ x, const float* __restrict__ a_s,
        float* __restrict__ out) {
    extern __shared__ char smem_raw[];
    const uint32_t sb = smem_u32(smem_raw);
    const int tid  = threadIdx.x;
    const int lane = tid & 31;
    const int wid  = tid >> 5;
    const int warp_m = wid & 3;            // 4 warps over M (32 rows each)
    const int warp_n = wid >> 2;           // 2 warps over N (64 cols each)

    // ---- Phase A: quantize one 128-row block of x (CTAs 0..MBLKS-1) ----
    const int blk = blockIdx.x;
    if (blk < MBLKS) {
        const float s = a_s[0];
        const float4* x4 = reinterpret_cast<const float4*>(x) + (size_t)blk * 24576;
        uint4* dst = reinterpret_cast<uint4*>(g_xq) + (size_t)blk * 6144;
        #pragma unroll
        for (int it = 0; it < 6144 / THREADS; it++) {
            int j = tid + it * THREADS;
            float4 v0 = __ldcs(&x4[j * 4 + 0]);
            float4 v1 = __ldcs(&x4[j * 4 + 1]);
            float4 v2 = __ldcs(&x4[j * 4 + 2]);
            float4 v3 = __ldcs(&x4[j * 4 + 3]);
            uint4 p;
            p.x = pack4(q8f(v0.x, s), q8f(v0.y, s), q8f(v0.z, s), q8f(v0.w, s));
            p.y = pack4(q8f(v1.x, s), q8f(v1.y, s), q8f(v1.z, s), q8f(v1.w, s));
            p.z = pack4(q8f(v2.x, s), q8f(v2.y, s), q8f(v2.z, s), q8f(v2.w, s));
            p.w = pack4(q8f(v3.x, s), q8f(v3.y, s), q8f(v3.z, s), q8f(v3.w, s));
            dst[j] = p;
        }
        __threadfence();       // all threads: make block stores gpu-visible
        __syncthreads();
        if (tid == 0) *(volatile int*)&g_flags[blk] = 1;
    }

    // ---- Phase B: persistent GEMM tile loop ----
    const float bs = g_bs;
    const uint32_t rA = (uint32_t)(warp_m * 32 + (lane & 15));
    const uint32_t rB = (uint32_t)(warp_n * 64 + (lane & 15));
    const uint32_t chalf = (uint32_t)((lane >> 4) & 1);
    const uint32_t r7 = (uint32_t)(lane & 7);

    for (int t = blockIdx.x; t < NTILES; t += gridDim.x) {
        const int mblk = t / NBLKS;
        const int nblk = t - mblk * NBLKS;
        const int m0 = mblk * BM;
        const int n0 = nblk * BN;

        // wait for this m-block's quantized A rows
        if (tid == 0) {
            while (*(volatile int*)&g_flags[mblk] == 0) { __nanosleep(64); }
        }
        __syncthreads();
        __threadfence();       // order flag observation before cp.async reads

        const int8_t* gA = g_xq + (size_t)m0 * DIN;
        const int8_t* gB = g_wq + (size_t)n0 * DIN;

        load_stage(sb + 0 * STAGE_BYTES, gA, gB, 0, tid);
        load_stage(sb + 1 * STAGE_BYTES, gA, gB, 1, tid);

        int acc[2][8][4];
        #pragma unroll
        for (int mi = 0; mi < 2; mi++)
            #pragma unroll
            for (int na = 0; na < 8; na++)
                #pragma unroll
                for (int q = 0; q < 4; q++) acc[mi][na][q] = 0;

        for (int kt = 0; kt < KT; kt++) {
            const int slot = kt % STAGES;
            if (kt == KT - 1) { CP_WAIT(0); } else { CP_WAIT(1); }
            __syncthreads();

            if (kt + 2 < KT)
                load_stage(sb + ((kt + 2) % STAGES) * STAGE_BYTES, gA, gB, kt + 2, tid);

            const uint32_t aS = sb + slot * STAGE_BYTES;
            const uint32_t bS = aS + A_BYTES;

            #pragma unroll
            for (int ks = 0; ks < 4; ks++) {   // 4 x k32 per 128B stage
                const uint32_t swc = (((2u * ks + chalf) ^ r7) << 4);
                uint32_t af[2][4];
                #pragma unroll
                for (int mi = 0; mi < 2; mi++)
                    LDSM_X4(af[mi], aS + (rA + mi * 16) * 128 + swc);
                uint32_t bf[4][4];
                #pragma unroll
                for (int nj = 0; nj < 4; nj++)
                    LDSM_X4(bf[nj], bS + (rB + nj * 16) * 128 + swc);
                #pragma unroll
                for (int mi = 0; mi < 2; mi++)
                    #pragma unroll
                    for (int na = 0; na < 8; na++) {
                        const int nj = na >> 1, hi = na & 1;
                        IMMA(acc[mi][na], af[mi], bf[nj][hi], bf[nj][hi + 2]);
                    }
            }
        }

        // epilogue: (acc + b_int) * b_s, direct float2 stores (exact math)
        const int g = lane >> 2, tig = lane & 3;
        #pragma unroll
        for (int mi = 0; mi < 2; mi++) {
            #pragma unroll
            for (int na = 0; na < 8; na++) {
                const int row = m0 + warp_m * 32 + mi * 16 + g;
                const int col = n0 + warp_n * 64 + na * 8 + 2 * tig;
                const float2 bi = *reinterpret_cast<const float2*>(&g_bint[col]);
                float2 v0, v1;
                v0.x = (__int2float_rn(acc[mi][na][0]) + bi.x) * bs;
                v0.y = (__int2float_rn(acc[mi][na][1]) + bi.y) * bs;
                v1.x = (__int2float_rn(acc[mi][na][2]) + bi.x) * bs;
                v1.y = (__int2float_rn(acc[mi][na][3]) + bi.y) * bs;
                *reinterpret_cast<float2*>(&out[(size_t)row * DOUT + col]) = v0;
                *reinterpret_cast<float2*>(&out[(size_t)(row + 8) * DOUT + col]) = v1;
            }
        }
        __syncthreads();   // keep smem reuse safe across tiles
    }
}

// ---------------- launch -----------------------------------------------------
extern "C" void kernel_launch(void* const* d_in, const int* in_sizes, int n_in,
                              void* d_out, int out_size) {
    const float *x = nullptr, *a_s = nullptr, *w = nullptr, *bias = nullptr;
    for (int i = 0; i < n_in; i++) {
        if      (in_sizes[i] == NTOK * DIN) x    = (const float*)d_in[i];
        else if (in_sizes[i] == 1)          a_s  = (const float*)d_in[i];
        else if (in_sizes[i] == DOUT * DIN) w    = (const float*)d_in[i];
        else if (in_sizes[i] == DOUT)       bias = (const float*)d_in[i];
    }
    float* out = (float*)d_out;

    cudaFuncSetAttribute(qlinear_fused, cudaFuncAttributeMaxDynamicSharedMemorySize, SMEM_BYTES);

    qlinear_wmax<<<1184, 256>>>(w);
    qlinear_prep<<<576, 256>>>(w, bias, a_s, out, (long long)out_size);
    qlinear_fused<<<GRID, THREADS, SMEM_BYTES>>>(x, a_s, out);
}

// round 10
// speedup vs baseline: 1.3061x; 1.3061x over previous
#include <cuda_runtime.h>
#include <cuda_bf16.h>
#include <cstdint>
#include <cstddef>

// ============================================================================
// QLinear via int8 IMMA (mma.sync m16n8k32 s8.s8.s32) — exact integer math.
// w_s = max|W|/127; b_s = w_s*a_s; out = (x_int @ w_int^T + b_int) * b_s
// R10: revert to R6 GEMM (77.6us measured floor; legacy IMMA rate-limited).
//      R9 fusion regressed (all CTAs quant before any GEMM -> no overlap).
//      New: wmax folded INTO quant_x (independent data, parallel), deleting
//      the 10us latency-bound wmax launch from the serial chain.
// ============================================================================

#define DEV_INLINE __device__ __forceinline__

namespace {
constexpr int NTOK = 32768;
constexpr int DIN  = 768;
constexpr int DOUT = 768;
constexpr long long NM = (long long)NTOK * DOUT;

constexpr int BM = 128;
constexpr int BN = 128;
constexpr int BK = 128;               // bytes of K per stage (int8)
constexpr int KT = DIN / BK;          // 6
constexpr int STAGES = 3;
constexpr int THREADS = 256;

constexpr int A_BYTES = BM * 128;     // 16384 (XOR swizzle, no pad)
constexpr int B_BYTES = BN * 128;     // 16384
constexpr int STAGE_BYTES = A_BYTES + B_BYTES;        // 32768
constexpr int SMEM_BYTES  = STAGES * STAGE_BYTES;     // 98304 -> 2 CTAs/SM

constexpr int WMAX_BLOCKS = 148;      // blocks of quant_x that also reduce W
} // namespace

// ---------------- device scratch (static: no runtime allocation) ------------
__device__ __align__(16) int8_t g_xq[(size_t)NTOK * DIN]; // 25.2 MB
__device__ __align__(16) int8_t g_wq[(size_t)DOUT * DIN]; // 0.59 MB
__device__ __align__(16) float  g_bint[DOUT];
__device__ unsigned int g_wmax_bits;                      // zero-init; atomicMax idempotent
__device__ float g_bs;

// ---------------- PTX helpers ------------------------------------------------
DEV_INLINE uint32_t smem_u32(const void* p) {
    uint32_t a;
    asm("{ .reg .u64 t; cvta.to.shared.u64 t, %1; cvt.u32.u64 %0, t; }" : "=r"(a) : "l"(p));
    return a;
}

#define CP16(dst, src) \
    asm volatile("cp.async.cg.shared.global [%0], [%1], 16;" :: "r"(dst), "l"(src))
#define CP_COMMIT() asm volatile("cp.async.commit_group;" ::: "memory")
#define CP_WAIT(n)  asm volatile("cp.async.wait_group %0;" :: "n"(n) : "memory")

#define LDSM_X4(r, addr)                                                        \
    asm volatile("ldmatrix.sync.aligned.m8n8.x4.shared.b16 {%0,%1,%2,%3}, [%4];" \
        : "=r"((r)[0]), "=r"((r)[1]), "=r"((r)[2]), "=r"((r)[3]) : "r"(addr))

#define IMMA(d, a, b0, b1)                                                      \
    asm volatile("mma.sync.aligned.m16n8k32.row.col.s32.s8.s8.s32 "             \
        "{%0,%1,%2,%3}, {%4,%5,%6,%7}, {%8,%9}, {%0,%1,%2,%3};"                 \
        : "+r"((d)[0]), "+r"((d)[1]), "+r"((d)[2]), "+r"((d)[3])                \
        : "r"((a)[0]), "r"((a)[1]), "r"((a)[2]), "r"((a)[3]), "r"(b0), "r"(b1))

// ---------------- quant helpers ----------------------------------------------
DEV_INLINE float q8f(float x, float s) {
    return fminf(fmaxf(rintf(__fdiv_rn(x, s)), -128.f), 127.f);
}
DEV_INLINE uint32_t pack4(float a, float b, float c, float d) {
    return (uint32_t)((int)a & 0xff) | ((uint32_t)((int)b & 0xff) << 8) |
           ((uint32_t)((int)c & 0xff) << 16) | ((uint32_t)((int)d & 0xff) << 24);
}

// ---------------- kernel 1: quant_x + embedded wmax --------------------------
// Blocks 0..WMAX_BLOCKS-1 additionally reduce max|W| over a private W slice
// (2.4MB total, +2.4% DRAM traffic under the DRAM-bound 100MB x read).
__global__ void qlinear_qx_wmax(const float* __restrict__ x,
                                const float* __restrict__ a_s,
                                const float* __restrict__ w) {
    // --- embedded wmax ---
    if (blockIdx.x < WMAX_BLOCKS) {
        const int n4w = (DOUT * DIN) >> 2;                  // 147456 float4
        const int per = (n4w + WMAX_BLOCKS - 1) / WMAX_BLOCKS; // 997
        const int lo = blockIdx.x * per;
        const int hi = min(lo + per, n4w);
        const float4* w4 = reinterpret_cast<const float4*>(w);
        float m = 0.f;
        for (int j = lo + threadIdx.x; j < hi; j += blockDim.x) {
            float4 v = w4[j];
            m = fmaxf(m, fmaxf(fmaxf(fabsf(v.x), fabsf(v.y)), fmaxf(fabsf(v.z), fabsf(v.w))));
        }
        #pragma unroll
        for (int o = 16; o; o >>= 1) m = fmaxf(m, __shfl_xor_sync(0xffffffffu, m, o));
        if ((threadIdx.x & 31) == 0) atomicMax(&g_wmax_bits, __float_as_uint(m));
    }

    // --- streaming quant of x ---
    const float s = a_s[0];
    const float4* x4 = reinterpret_cast<const float4*>(x);
    uint4* dst = reinterpret_cast<uint4*>(g_xq);
    int n16 = (NTOK * DIN) >> 4;
    for (int j = blockIdx.x * blockDim.x + threadIdx.x; j < n16; j += gridDim.x * blockDim.x) {
        float4 v0 = __ldcs(&x4[j * 4 + 0]);
        float4 v1 = __ldcs(&x4[j * 4 + 1]);
        float4 v2 = __ldcs(&x4[j * 4 + 2]);
        float4 v3 = __ldcs(&x4[j * 4 + 3]);
        uint4 p;
        p.x = pack4(q8f(v0.x, s), q8f(v0.y, s), q8f(v0.z, s), q8f(v0.w, s));
        p.y = pack4(q8f(v1.x, s), q8f(v1.y, s), q8f(v1.z, s), q8f(v1.w, s));
        p.z = pack4(q8f(v2.x, s), q8f(v2.y, s), q8f(v2.z, s), q8f(v2.w, s));
        p.w = pack4(q8f(v3.x, s), q8f(v3.y, s), q8f(v3.z, s), q8f(v3.w, s));
        dst[j] = p;
    }
}

// ---------------- kernel 2: prep (bs + W/bias quant + out tail) --------------
__global__ void qlinear_prep(const float* __restrict__ w,
                             const float* __restrict__ bias,
                             const float* __restrict__ a_s,
                             float* __restrict__ out, long long out_size) {
    const float ws = __fdiv_rn(__uint_as_float(g_wmax_bits), 127.0f);
    const float bs = __fmul_rn(ws, a_s[0]);

    if (blockIdx.x == 0) {
        if (threadIdx.x == 0) g_bs = bs;
        for (long long i = NM + threadIdx.x; i < out_size; i += blockDim.x) out[i] = bs;
        for (int i = threadIdx.x; i < DOUT; i += blockDim.x) {
            float q = rintf(__fdiv_rn(bias[i], bs));
            g_bint[i] = fminf(fmaxf(q, -2147483648.f), 2147483648.f);
        }
    }

    const float4* w4 = reinterpret_cast<const float4*>(w);
    uint32_t* dst = reinterpret_cast<uint32_t*>(g_wq);
    int n4 = (DOUT * DIN) >> 2;
    for (int j = blockIdx.x * blockDim.x + threadIdx.x; j < n4; j += gridDim.x * blockDim.x) {
        float4 v = w4[j];
        dst[j] = pack4(q8f(v.x, ws), q8f(v.y, ws), q8f(v.z, ws), q8f(v.w, ws));
    }
}

// ---------------- GEMM (R6 config: 8 warps, 32x64 warp tile, 2 CTA/SM) -------
// XOR swizzle: byte chunk c (16B units, 0..7 within a 128B row) -> c ^ (row&7).
DEV_INLINE uint32_t swz(uint32_t row, uint32_t c16) {
    return row * 128u + ((c16 ^ (row & 7u)) << 4);
}

DEV_INLINE void load_stage(uint32_t sbase, const int8_t* gA, const int8_t* gB,
                           int kt, int tid) {
    const int kbase = kt * BK;
    #pragma unroll
    for (int j = 0; j < 4; j++) {          // A: 128 rows x 8 chunks of 16B = 1024
        int idx = tid + j * THREADS;
        uint32_t r = idx >> 3, c = idx & 7;
        CP16(sbase + swz(r, c), gA + (size_t)r * DIN + kbase + c * 16);
    }
    #pragma unroll
    for (int j = 0; j < 4; j++) {          // B: 128 rows x 8 chunks of 16B = 1024
        int idx = tid + j * THREADS;
        uint32_t r = idx >> 3, c = idx & 7;
        CP16(sbase + A_BYTES + swz(r, c), gB + (size_t)r * DIN + kbase + c * 16);
    }
    CP_COMMIT();
}

__global__ __launch_bounds__(THREADS, 2) void qlinear_gemm(float* __restrict__ out) {
    extern __shared__ char smem_raw[];
    const uint32_t sb = smem_u32(smem_raw);
    const int tid  = threadIdx.x;
    const int lane = tid & 31;
    const int wid  = tid >> 5;
    const int warp_m = wid & 3;            // 4 warps over M (32 rows each)
    const int warp_n = wid >> 2;           // 2 warps over N (64 cols each)
    const int m0 = blockIdx.y * BM;
    const int n0 = blockIdx.x * BN;

    const int8_t* gA = g_xq + (size_t)m0 * DIN;
    const int8_t* gB = g_wq + (size_t)n0 * DIN;

    // prologue
    load_stage(sb + 0 * STAGE_BYTES, gA, gB, 0, tid);
    load_stage(sb + 1 * STAGE_BYTES, gA, gB, 1, tid);

    int acc[2][8][4];
    #pragma unroll
    for (int mi = 0; mi < 2; mi++)
        #pragma unroll
        for (int na = 0; na < 8; na++)
            #pragma unroll
            for (int q = 0; q < 4; q++) acc[mi][na][q] = 0;

    const uint32_t rA = (uint32_t)(warp_m * 32 + (lane & 15));
    const uint32_t rB = (uint32_t)(warp_n * 64 + (lane & 15));
    const uint32_t chalf = (uint32_t)((lane >> 4) & 1);
    const uint32_t r7 = (uint32_t)(lane & 7);

    for (int kt = 0; kt < KT; kt++) {
        const int slot = kt % STAGES;
        if (kt == KT - 1) { CP_WAIT(0); } else { CP_WAIT(1); }
        __syncthreads();

        if (kt + 2 < KT)
            load_stage(sb + ((kt + 2) % STAGES) * STAGE_BYTES, gA, gB, kt + 2, tid);

        const uint32_t aS = sb + slot * STAGE_BYTES;
        const uint32_t bS = aS + A_BYTES;

        #pragma unroll
        for (int ks = 0; ks < 4; ks++) {   // 4 x k32 per 128B stage
            const uint32_t swc = (((2u * ks + chalf) ^ r7) << 4);
            uint32_t af[2][4];
            #pragma unroll
            for (int mi = 0; mi < 2; mi++)
                LDSM_X4(af[mi], aS + (rA + mi * 16) * 128 + swc);
            uint32_t bf[4][4];
            #pragma unroll
            for (int nj = 0; nj < 4; nj++)
                LDSM_X4(bf[nj], bS + (rB + nj * 16) * 128 + swc);
            #pragma unroll
            for (int mi = 0; mi < 2; mi++)
                #pragma unroll
                for (int na = 0; na < 8; na++) {
                    const int nj = na >> 1, hi = na & 1;
                    IMMA(acc[mi][na], af[mi], bf[nj][hi], bf[nj][hi + 2]);
                }
        }
    }

    // epilogue: (acc + b_int) * b_s, direct float2 global stores (exact math)
    const float bs = g_bs;
    const int g = lane >> 2, tig = lane & 3;
    #pragma unroll
    for (int mi = 0; mi < 2; mi++) {
        #pragma unroll
        for (int na = 0; na < 8; na++) {
            const int row = m0 + warp_m * 32 + mi * 16 + g;
            const int col = n0 + warp_n * 64 + na * 8 + 2 * tig;
            const float2 bi = *reinterpret_cast<const float2*>(&g_bint[col]);
            float2 v0, v1;
            v0.x = (__int2float_rn(acc[mi][na][0]) + bi.x) * bs;
            v0.y = (__int2float_rn(acc[mi][na][1]) + bi.y) * bs;
            v1.x = (__int2float_rn(acc[mi][na][2]) + bi.x) * bs;
            v1.y = (__int2float_rn(acc[mi][na][3]) + bi.y) * bs;
            *reinterpret_cast<float2*>(&out[(size_t)row * DOUT + col]) = v0;
            *reinterpret_cast<float2*>(&out[(size_t)(row + 8) * DOUT + col]) = v1;
        }
    }
}

// ---------------- launch -----------------------------------------------------
extern "C" void kernel_launch(void* const* d_in, const int* in_sizes, int n_in,
                              void* d_out, int out_size) {
    const float *x = nullptr, *a_s = nullptr, *w = nullptr, *bias = nullptr;
    for (int i = 0; i < n_in; i++) {
        if      (in_sizes[i] == NTOK * DIN) x    = (const float*)d_in[i];
        else if (in_sizes[i] == 1)          a_s  = (const float*)d_in[i];
        else if (in_sizes[i] == DOUT * DIN) w    = (const float*)d_in[i];
        else if (in_sizes[i] == DOUT)       bias = (const float*)d_in[i];
    }
    float* out = (float*)d_out;

    cudaFuncSetAttribute(qlinear_gemm, cudaFuncAttributeMaxDynamicSharedMemorySize, SMEM_BYTES);

    qlinear_qx_wmax<<<3072, 512>>>(x, a_s, w);
    qlinear_prep<<<576, 256>>>(w, bias, a_s, out, (long long)out_size);

    dim3 grid(DOUT / BN, NTOK / BM);   // (6, 256) = 1536 CTAs
    qlinear_gemm<<<grid, THREADS, SMEM_BYTES>>>(out);
}

// round 11
// speedup vs baseline: 1.3878x; 1.0625x over previous
#include <cuda_runtime.h>
#include <cuda_bf16.h>
#include <cstdint>
#include <cstddef>

// ============================================================================
// QLinear via int8 IMMA (mma.sync m16n8k32 s8.s8.s32) — exact integer math.
// w_s = max|W|/127; b_s = w_s*a_s; out = (x_int @ w_int^T + b_int) * b_s
// R11: quant_x math slimmed (FMUL + CVT.rni.s32 + int clamp + PRMT pack,
//      reciprocal hoisted) — R10 profile showed qx_wmax issue-bound (48.2%
//      issue, only 46.7% DRAM). GEMM unchanged (R6 config, 77.6us floor).
// ============================================================================

#define DEV_INLINE __device__ __forceinline__

namespace {
constexpr int NTOK = 32768;
constexpr int DIN  = 768;
constexpr int DOUT = 768;
constexpr long long NM = (long long)NTOK * DOUT;

constexpr int BM = 128;
constexpr int BN = 128;
constexpr int BK = 128;               // bytes of K per stage (int8)
constexpr int KT = DIN / BK;          // 6
constexpr int STAGES = 3;
constexpr int THREADS = 256;

constexpr int A_BYTES = BM * 128;     // 16384 (XOR swizzle, no pad)
constexpr int B_BYTES = BN * 128;     // 16384
constexpr int STAGE_BYTES = A_BYTES + B_BYTES;        // 32768
constexpr int SMEM_BYTES  = STAGES * STAGE_BYTES;     // 98304 -> 2 CTAs/SM

constexpr int WMAX_BLOCKS = 148;      // blocks of quant_x that also reduce W
} // namespace

// ---------------- device scratch (static: no runtime allocation) ------------
__device__ __align__(16) int8_t g_xq[(size_t)NTOK * DIN]; // 25.2 MB
__device__ __align__(16) int8_t g_wq[(size_t)DOUT * DIN]; // 0.59 MB
__device__ __align__(16) float  g_bint[DOUT];
__device__ unsigned int g_wmax_bits;                      // zero-init; atomicMax idempotent
__device__ float g_bs;

// ---------------- PTX helpers ------------------------------------------------
DEV_INLINE uint32_t smem_u32(const void* p) {
    uint32_t a;
    asm("{ .reg .u64 t; cvta.to.shared.u64 t, %1; cvt.u32.u64 %0, t; }" : "=r"(a) : "l"(p));
    return a;
}

#define CP16(dst, src) \
    asm volatile("cp.async.cg.shared.global [%0], [%1], 16;" :: "r"(dst), "l"(src))
#define CP_COMMIT() asm volatile("cp.async.commit_group;" ::: "memory")
#define CP_WAIT(n)  asm volatile("cp.async.wait_group %0;" :: "n"(n) : "memory")

#define LDSM_X4(r, addr)                                                        \
    asm volatile("ldmatrix.sync.aligned.m8n8.x4.shared.b16 {%0,%1,%2,%3}, [%4];" \
        : "=r"((r)[0]), "=r"((r)[1]), "=r"((r)[2]), "=r"((r)[3]) : "r"(addr))

#define IMMA(d, a, b0, b1)                                                      \
    asm volatile("mma.sync.aligned.m16n8k32.row.col.s32.s8.s8.s32 "             \
        "{%0,%1,%2,%3}, {%4,%5,%6,%7}, {%8,%9}, {%0,%1,%2,%3};"                 \
        : "+r"((d)[0]), "+r"((d)[1]), "+r"((d)[2]), "+r"((d)[3])                \
        : "r"((a)[0]), "r"((a)[1]), "r"((a)[2]), "r"((a)[3]), "r"(b0), "r"(b1))

// ---------------- quant helpers ----------------------------------------------
DEV_INLINE float q8f(float x, float s) {            // exact path (W, bias)
    return fminf(fmaxf(rintf(__fdiv_rn(x, s)), -128.f), 127.f);
}
DEV_INLINE uint32_t pack4(float a, float b, float c, float d) {
    return (uint32_t)((int)a & 0xff) | ((uint32_t)((int)b & 0xff) << 8) |
           ((uint32_t)((int)c & 0xff) << 16) | ((uint32_t)((int)d & 0xff) << 24);
}
// fast path (x): y = x*r; round-nearest-even to int; clamp in int domain
DEV_INLINE int q8i(float x, float r) {
    int q = __float2int_rn(x * r);                  // FMUL + CVT.rni.s32.f32
    return max(-128, min(127, q));                  // IMNMX x2
}
DEV_INLINE uint32_t pack4i(int a, int b, int c, int d) {
    uint32_t lo = __byte_perm((uint32_t)a, (uint32_t)b, 0x0040); // [b.b0 a.b0]
    uint32_t hi = __byte_perm((uint32_t)c, (uint32_t)d, 0x0040); // [d.b0 c.b0]
    return __byte_perm(lo, hi, 0x5410);             // [d c b a]
}

// ---------------- kernel 1: quant_x + embedded wmax --------------------------
__global__ void qlinear_qx_wmax(const float* __restrict__ x,
                                const float* __restrict__ a_s,
                                const float* __restrict__ w) {
    // --- embedded wmax (blocks 0..147 reduce a private W slice) ---
    if (blockIdx.x < WMAX_BLOCKS) {
        const int n4w = (DOUT * DIN) >> 2;                  // 147456 float4
        const int per = (n4w + WMAX_BLOCKS - 1) / WMAX_BLOCKS;
        const int lo = blockIdx.x * per;
        const int hi = min(lo + per, n4w);
        const float4* w4 = reinterpret_cast<const float4*>(w);
        float m = 0.f;
        for (int j = lo + threadIdx.x; j < hi; j += blockDim.x) {
            float4 v = w4[j];
            m = fmaxf(m, fmaxf(fmaxf(fabsf(v.x), fabsf(v.y)), fmaxf(fabsf(v.z), fabsf(v.w))));
        }
        #pragma unroll
        for (int o = 16; o; o >>= 1) m = fmaxf(m, __shfl_xor_sync(0xffffffffu, m, o));
        if ((threadIdx.x & 31) == 0) atomicMax(&g_wmax_bits, __float_as_uint(m));
    }

    // --- streaming quant of x (slim math) ---
    const float r = __fdiv_rn(1.0f, a_s[0]);
    const float4* x4 = reinterpret_cast<const float4*>(x);
    uint4* dst = reinterpret_cast<uint4*>(g_xq);
    int n16 = (NTOK * DIN) >> 4;
    for (int j = blockIdx.x * blockDim.x + threadIdx.x; j < n16; j += gridDim.x * blockDim.x) {
        float4 v0 = __ldcs(&x4[j * 4 + 0]);
        float4 v1 = __ldcs(&x4[j * 4 + 1]);
        float4 v2 = __ldcs(&x4[j * 4 + 2]);
        float4 v3 = __ldcs(&x4[j * 4 + 3]);
        uint4 p;
        p.x = pack4i(q8i(v0.x, r), q8i(v0.y, r), q8i(v0.z, r), q8i(v0.w, r));
        p.y = pack4i(q8i(v1.x, r), q8i(v1.y, r), q8i(v1.z, r), q8i(v1.w, r));
        p.z = pack4i(q8i(v2.x, r), q8i(v2.y, r), q8i(v2.z, r), q8i(v2.w, r));
        p.w = pack4i(q8i(v3.x, r), q8i(v3.y, r), q8i(v3.z, r), q8i(v3.w, r));
        dst[j] = p;
    }
}

// ---------------- kernel 2: prep (bs + W/bias quant + out tail) --------------
__global__ void qlinear_prep(const float* __restrict__ w,
                             const float* __restrict__ bias,
                             const float* __restrict__ a_s,
                             float* __restrict__ out, long long out_size) {
    const float ws = __fdiv_rn(__uint_as_float(g_wmax_bits), 127.0f);
    const float bs = __fmul_rn(ws, a_s[0]);

    if (blockIdx.x == 0) {
        if (threadIdx.x == 0) g_bs = bs;
        for (long long i = NM + threadIdx.x; i < out_size; i += blockDim.x) out[i] = bs;
        for (int i = threadIdx.x; i < DOUT; i += blockDim.x) {
            float q = rintf(__fdiv_rn(bias[i], bs));
            g_bint[i] = fminf(fmaxf(q, -2147483648.f), 2147483648.f);
        }
    }

    const float4* w4 = reinterpret_cast<const float4*>(w);
    uint32_t* dst = reinterpret_cast<uint32_t*>(g_wq);
    int n4 = (DOUT * DIN) >> 2;
    for (int j = blockIdx.x * blockDim.x + threadIdx.x; j < n4; j += gridDim.x * blockDim.x) {
        float4 v = w4[j];
        dst[j] = pack4(q8f(v.x, ws), q8f(v.y, ws), q8f(v.z, ws), q8f(v.w, ws));
    }
}

// ---------------- GEMM (R6 config: 8 warps, 32x64 warp tile, 2 CTA/SM) -------
DEV_INLINE uint32_t swz(uint32_t row, uint32_t c16) {
    return row * 128u + ((c16 ^ (row & 7u)) << 4);
}

DEV_INLINE void load_stage(uint32_t sbase, const int8_t* gA, const int8_t* gB,
                           int kt, int tid) {
    const int kbase = kt * BK;
    #pragma unroll
    for (int j = 0; j < 4; j++) {          // A: 128 rows x 8 chunks of 16B
        int idx = tid + j * THREADS;
        uint32_t r = idx >> 3, c = idx & 7;
        CP16(sbase + swz(r, c), gA + (size_t)r * DIN + kbase + c * 16);
    }
    #pragma unroll
    for (int j = 0; j < 4; j++) {          // B: 128 rows x 8 chunks of 16B
        int idx = tid + j * THREADS;
        uint32_t r = idx >> 3, c = idx & 7;
        CP16(sbase + A_BYTES + swz(r, c), gB + (size_t)r * DIN + kbase + c * 16);
    }
    CP_COMMIT();
}

__global__ __launch_bounds__(THREADS, 2) void qlinear_gemm(float* __restrict__ out) {
    extern __shared__ char smem_raw[];
    const uint32_t sb = smem_u32(smem_raw);
    const int tid  = threadIdx.x;
    const int lane = tid & 31;
    const int wid  = tid >> 5;
    const int warp_m = wid & 3;            // 4 warps over M (32 rows each)
    const int warp_n = wid >> 2;           // 2 warps over N (64 cols each)
    const int m0 = blockIdx.y * BM;
    const int n0 = blockIdx.x * BN;

    const int8_t* gA = g_xq + (size_t)m0 * DIN;
    const int8_t* gB = g_wq + (size_t)n0 * DIN;

    load_stage(sb + 0 * STAGE_BYTES, gA, gB, 0, tid);
    load_stage(sb + 1 * STAGE_BYTES, gA, gB, 1, tid);

    int acc[2][8][4];
    #pragma unroll
    for (int mi = 0; mi < 2; mi++)
        #pragma unroll
        for (int na = 0; na < 8; na++)
            #pragma unroll
            for (int q = 0; q < 4; q++) acc[mi][na][q] = 0;

    const uint32_t rA = (uint32_t)(warp_m * 32 + (lane & 15));
    const uint32_t rB = (uint32_t)(warp_n * 64 + (lane & 15));
    const uint32_t chalf = (uint32_t)((lane >> 4) & 1);
    const uint32_t r7 = (uint32_t)(lane & 7);

    for (int kt = 0; kt < KT; kt++) {
        const int slot = kt % STAGES;
        if (kt == KT - 1) { CP_WAIT(0); } else { CP_WAIT(1); }
        __syncthreads();

        if (kt + 2 < KT)
            load_stage(sb + ((kt + 2) % STAGES) * STAGE_BYTES, gA, gB, kt + 2, tid);

        const uint32_t aS = sb + slot * STAGE_BYTES;
        const uint32_t bS = aS + A_BYTES;

        #pragma unroll
        for (int ks = 0; ks < 4; ks++) {   // 4 x k32 per 128B stage
            const uint32_t swc = (((2u * ks + chalf) ^ r7) << 4);
            uint32_t af[2][4];
            #pragma unroll
            for (int mi = 0; mi < 2; mi++)
                LDSM_X4(af[mi], aS + (rA + mi * 16) * 128 + swc);
            uint32_t bf[4][4];
            #pragma unroll
            for (int nj = 0; nj < 4; nj++)
                LDSM_X4(bf[nj], bS + (rB + nj * 16) * 128 + swc);
            #pragma unroll
            for (int mi = 0; mi < 2; mi++)
                #pragma unroll
                for (int na = 0; na < 8; na++) {
                    const int nj = na >> 1, hi = na & 1;
                    IMMA(acc[mi][na], af[mi], bf[nj][hi], bf[nj][hi + 2]);
                }
        }
    }

    // epilogue: (acc + b_int) * b_s, direct float2 global stores (exact math)
    const float bs = g_bs;
    const int g = lane >> 2, tig = lane & 3;
    #pragma unroll
    for (int mi = 0; mi < 2; mi++) {
        #pragma unroll
        for (int na = 0; na < 8; na++) {
            const int row = m0 + warp_m * 32 + mi * 16 + g;
            const int col = n0 + warp_n * 64 + na * 8 + 2 * tig;
            const float2 bi = *reinterpret_cast<const float2*>(&g_bint[col]);
            float2 v0, v1;
            v0.x = (__int2float_rn(acc[mi][na][0]) + bi.x) * bs;
            v0.y = (__int2float_rn(acc[mi][na][1]) + bi.y) * bs;
            v1.x = (__int2float_rn(acc[mi][na][2]) + bi.x) * bs;
            v1.y = (__int2float_rn(acc[mi][na][3]) + bi.y) * bs;
            *reinterpret_cast<float2*>(&out[(size_t)row * DOUT + col]) = v0;
            *reinterpret_cast<float2*>(&out[(size_t)(row + 8) * DOUT + col]) = v1;
        }
    }
}

// ---------------- launch -----------------------------------------------------
extern "C" void kernel_launch(void* const* d_in, const int* in_sizes, int n_in,
                              void* d_out, int out_size) {
    const float *x = nullptr, *a_s = nullptr, *w = nullptr, *bias = nullptr;
    for (int i = 0; i < n_in; i++) {
        if      (in_sizes[i] == NTOK * DIN) x    = (const float*)d_in[i];
        else if (in_sizes[i] == 1)          a_s  = (const float*)d_in[i];
        else if (in_sizes[i] == DOUT * DIN) w    = (const float*)d_in[i];
        else if (in_sizes[i] == DOUT)       bias = (const float*)d_in[i];
    }
    float* out = (float*)d_out;

    cudaFuncSetAttribute(qlinear_gemm, cudaFuncAttributeMaxDynamicSharedMemorySize, SMEM_BYTES);

    qlinear_qx_wmax<<<3072, 512>>>(x, a_s, w);
    qlinear_prep<<<576, 256>>>(w, bias, a_s, out, (long long)out_size);

    dim3 grid(DOUT / BN, NTOK / BM);   // (6, 256) = 1536 CTAs
    qlinear_gemm<<<grid, THREADS, SMEM_BYTES>>>(out);
}